// round 2
// baseline (speedup 1.0000x reference)
#include <cuda_runtime.h>
#include <math.h>

#define HH 768
#define WW 768
#define LL 8
#define PP 36
#define NPIX (HH*WW)

#define C_SIGMAP (1.0f / 11.0f)   /* 1/(3+L) */
#define C_LMBDA  0.1f
#define C_NU     0.01f
#define C_TAUU   (1.0f / 6.0f)
#define C_TAUM   (1.0f / 11.0f)   /* 1/(2+PROJ/4) */

// ---- scratch (allocation-free rule: device globals) ----
__device__ float g_p1[NPIX * LL];
__device__ float g_p2[NPIX * LL];
__device__ float g_p3[NPIX * LL];
__device__ float g_mu1[NPIX * PP];
__device__ float g_mu2[NPIX * PP];
__device__ float g_u [NPIX * LL];
__device__ float g_ub[NPIX * LL];

// K -> (k1,k2) for the upper-triangular combo ordering (k1 outer, k2 inner)
__device__ __host__ constexpr int kk1(int K) {
    int k1 = 0, r = K, c = LL;
    while (r >= c) { r -= c; k1++; c--; }
    return k1;
}
__device__ __host__ constexpr int kk2(int K) {
    int k1 = 0, r = K, c = LL;
    while (r >= c) { r -= c; k1++; c--; }
    return k1 + r;
}

__device__ __forceinline__ void ld8(const float* __restrict__ p, float* v) {
    float4 a = *(const float4*)p;
    float4 b = *(const float4*)(p + 4);
    v[0]=a.x; v[1]=a.y; v[2]=a.z; v[3]=a.w;
    v[4]=b.x; v[5]=b.y; v[6]=b.z; v[7]=b.w;
}
__device__ __forceinline__ void st8(float* __restrict__ p, const float* v) {
    *(float4*)p       = make_float4(v[0], v[1], v[2], v[3]);
    *(float4*)(p + 4) = make_float4(v[4], v[5], v[6], v[7]);
}

// =====================================================================
// Kernel A: parabola (+ fused l2projection & mu-update when FULL)
// One thread per pixel; all L=8 levels + PROJ=36 combos in registers.
// =====================================================================
template <bool FULL>
__global__ __launch_bounds__(256)
void kernA(const float* __restrict__ ubar,
           const float* __restrict__ p1i, const float* __restrict__ p2i, const float* __restrict__ p3i,
           const float* __restrict__ mu1i, const float* __restrict__ mu2i,
           const float* __restrict__ s1i,  const float* __restrict__ s2i,
           const float* __restrict__ mb1i, const float* __restrict__ mb2i,
           const float* __restrict__ f,
           float* __restrict__ p1o, float* __restrict__ p2o, float* __restrict__ p3o,
           float* __restrict__ mu1o, float* __restrict__ mu2o)
{
    int pix = blockIdx.x * blockDim.x + threadIdx.x;
    if (pix >= NPIX) return;
    int w = pix % WW;
    int h = pix / WW;

    // ---- forward differences of ubar ----
    float ub[LL];
    ld8(ubar + pix * LL, ub);
    float u1[LL], u2[LL], u3[LL];
    if (h < HH - 1) {
        float nb[LL]; ld8(ubar + (pix + WW) * LL, nb);
        #pragma unroll
        for (int z = 0; z < LL; z++) u1[z] = nb[z] - ub[z];
    } else {
        #pragma unroll
        for (int z = 0; z < LL; z++) u1[z] = 0.0f;
    }
    if (w < WW - 1) {
        float nb[LL]; ld8(ubar + (pix + 1) * LL, nb);
        #pragma unroll
        for (int z = 0; z < LL; z++) u2[z] = nb[z] - ub[z];
    } else {
        #pragma unroll
        for (int z = 0; z < LL; z++) u2[z] = 0.0f;
    }
    #pragma unroll
    for (int z = 0; z < LL; z++) u3[z] = (z < LL - 1) ? (ub[z + 1] - ub[z]) : 0.0f;

    // ---- membership sums over combos:  musum[z] = sum_{K: k1<=z<=k2} mu[K] ----
    float m1s[LL], m2s[LL];
    #pragma unroll
    for (int z = 0; z < LL; z++) { m1s[z] = 0.0f; m2s[z] = 0.0f; }
    const float4* m1p = (const float4*)(mu1i + pix * PP);
    const float4* m2p = (const float4*)(mu2i + pix * PP);
    #pragma unroll
    for (int i = 0; i < 9; i++) {
        float4 q1 = m1p[i];
        float4 q2 = m2p[i];
        float v1[4] = {q1.x, q1.y, q1.z, q1.w};
        float v2[4] = {q2.x, q2.y, q2.z, q2.w};
        #pragma unroll
        for (int j = 0; j < 4; j++) {
            const int K = 4 * i + j;
            #pragma unroll
            for (int z = 0; z < LL; z++) {
                if (z >= kk1(K) && z <= kk2(K)) { m1s[z] += v1[j]; m2s[z] += v2[j]; }
            }
        }
    }

    // ---- parabola projection ----
    float p1v[LL], p2v[LL], p3v[LL];
    ld8(p1i + pix * LL, p1v);
    ld8(p2i + pix * LL, p2v);
    ld8(p3i + pix * LL, p3v);
    float fv = __ldg(f + pix);

    float P1[LL], P2[LL], P3[LL];
    #pragma unroll
    for (int z = 0; z < LL; z++) {
        float U1 = p1v[z] + C_SIGMAP * (u1[z] + m1s[z]);
        float U2 = p2v[z] + C_SIGMAP * (u2[z] + m2s[z]);
        float U3 = p3v[z] + C_SIGMAP * u3[z];
        float t   = (float)(z + 1) * (1.0f / (float)LL) - fv;
        float quad = C_LMBDA * t * t;
        float n2  = U1 * U1 + U2 * U2;
        float B   = 0.25f * n2 - quad;
        float r1 = U1, r2 = U2, r3 = U3;
        if (U3 < B) {
            float y   = U3 + quad;
            float nrm = sqrtf(n2);
            float a   = 0.5f * nrm;
            float b   = (2.0f / 3.0f) * (1.0f - 0.5f * y);
            float sb  = sqrtf(fmaxf(-b, 0.0f));
            float sb3 = sb * sb * sb;
            float d   = (b < 0.0f) ? (a - sb3) * (a + sb3) : (a * a + b * b * b);
            float v;
            if (d < 0.0f) {
                float sb3s = (sb > 0.0f) ? sb3 : 1.0f;
                float ca = fminf(fmaxf(a / sb3s, -1.0f), 1.0f);
                v = 2.0f * sb * cosf(acosf(ca) * (1.0f / 3.0f));
            } else {
                float sd = sqrtf(d);
                float c  = cbrtf(a + sd);
                v = (c == 0.0f) ? 0.0f : (c - b / c);
            }
            if (nrm == 0.0f) { r1 = 0.0f; r2 = 0.0f; }
            else             { float s = 2.0f * v / nrm; r1 = s * U1; r2 = s * U2; }
            r3 = 0.25f * (r1 * r1 + r2 * r2) - quad;
        }
        P1[z] = r1; P2[z] = r2; P3[z] = r3;
    }
    st8(p1o + pix * LL, P1);
    st8(p2o + pix * LL, P2);
    st8(p3o + pix * LL, P3);

    // ---- fused l2projection + mu update (iteration 1 only) ----
    if (FULL) {
        float c1[LL + 1], c2[LL + 1];
        c1[0] = 0.0f; c2[0] = 0.0f;
        #pragma unroll
        for (int z = 0; z < LL; z++) { c1[z + 1] = c1[z] + P1[z]; c2[z + 1] = c2[z] + P2[z]; }

        const float4* s1p = (const float4*)(s1i  + pix * PP);
        const float4* s2p = (const float4*)(s2i  + pix * PP);
        const float4* b1p = (const float4*)(mb1i + pix * PP);
        const float4* b2p = (const float4*)(mb2i + pix * PP);
        float4* o1 = (float4*)(mu1o + pix * PP);
        float4* o2 = (float4*)(mu2o + pix * PP);

        #pragma unroll
        for (int i = 0; i < 9; i++) {
            float4 qs1 = __ldcs(s1p + i);
            float4 qs2 = __ldcs(s2p + i);
            float4 qb1 = __ldcs(b1p + i);
            float4 qb2 = __ldcs(b2p + i);
            float4 qm1 = m1p[i];      // L1-hot (re-read from pass 1)
            float4 qm2 = m2p[i];
            float vs1[4] = {qs1.x, qs1.y, qs1.z, qs1.w};
            float vs2[4] = {qs2.x, qs2.y, qs2.z, qs2.w};
            float vb1[4] = {qb1.x, qb1.y, qb1.z, qb1.w};
            float vb2[4] = {qb2.x, qb2.y, qb2.z, qb2.w};
            float vm1[4] = {qm1.x, qm1.y, qm1.z, qm1.w};
            float vm2[4] = {qm2.x, qm2.y, qm2.z, qm2.w};
            float r1o[4], r2o[4];
            #pragma unroll
            for (int j = 0; j < 4; j++) {
                const int K = 4 * i + j;
                // l2projection (SIGMAS = 1)
                float a1 = vs1[j] - vb1[j];
                float a2 = vs2[j] - vb2[j];
                float nr = sqrtf(a1 * a1 + a2 * a2);
                if (nr > C_NU) { float rr = C_NU / nr; a1 *= rr; a2 *= rr; }
                // adjoint membership sums via prefix differences
                float t1 = c1[kk2(K) + 1] - c1[kk1(K)];
                float t2 = c2[kk2(K) + 1] - c2[kk1(K)];
                r1o[j] = vm1[j] + C_TAUM * (a1 - t1);
                r2o[j] = vm2[j] + C_TAUM * (a2 - t2);
            }
            o1[i] = make_float4(r1o[0], r1o[1], r1o[2], r1o[3]);
            o2[i] = make_float4(r2o[0], r2o[1], r2o[2], r2o[3]);
        }
    }
}

// =====================================================================
// Kernel B: clipping (divergence + clamp + over-relaxation)
// =====================================================================
template <bool WRITE_UBAR>
__global__ __launch_bounds__(256)
void kernB(const float* __restrict__ ui,
           const float* __restrict__ p1, const float* __restrict__ p2, const float* __restrict__ p3,
           float* __restrict__ uo, float* __restrict__ ubo)
{
    int pix = blockIdx.x * blockDim.x + threadIdx.x;
    if (pix >= NPIX) return;
    int w = pix % WW;
    int h = pix / WW;

    float uv[LL];  ld8(ui + pix * LL, uv);
    float p1c[LL]; ld8(p1 + pix * LL, p1c);
    float p2c[LL]; ld8(p2 + pix * LL, p2c);
    float p3c[LL]; ld8(p3 + pix * LL, p3c);

    float p1u[LL], p2l[LL];
    if (h > 0) {
        ld8(p1 + (pix - WW) * LL, p1u);
    } else {
        #pragma unroll
        for (int z = 0; z < LL; z++) p1u[z] = 0.0f;
    }
    if (w > 0) {
        ld8(p2 + (pix - 1) * LL, p2l);
    } else {
        #pragma unroll
        for (int z = 0; z < LL; z++) p2l[z] = 0.0f;
    }

    float ch = (h < HH - 1) ? 1.0f : 0.0f;   // zero last slice along h for p1
    float cw = (w < WW - 1) ? 1.0f : 0.0f;   // zero last slice along w for p2

    float un[LL], ubv[LL];
    #pragma unroll
    for (int z = 0; z < LL; z++) {
        float d1 = ch * p1c[z] - p1u[z];
        float d2 = cw * p2c[z] - p2l[z];
        float d3 = ((z < LL - 1) ? p3c[z] : 0.0f) - ((z > 0) ? p3c[z - 1] : 0.0f);
        float v  = uv[z] + C_TAUU * (d1 + d2 + d3);
        v = fminf(fmaxf(v, 0.0f), 1.0f);
        un[z]  = v;
        ubv[z] = 2.0f * v - uv[z];
    }
    st8(uo + pix * LL, un);
    if (WRITE_UBAR) st8(ubo + pix * LL, ubv);
}

// =====================================================================
extern "C" void kernel_launch(void* const* d_in, const int* in_sizes, int n_in,
                              void* d_out, int out_size)
{
    const float* u    = (const float*)d_in[0];
    const float* ubar = (const float*)d_in[1];
    const float* p1   = (const float*)d_in[2];
    const float* p2   = (const float*)d_in[3];
    const float* p3   = (const float*)d_in[4];
    const float* s1   = (const float*)d_in[5];
    const float* s2   = (const float*)d_in[6];
    const float* mu1  = (const float*)d_in[7];
    const float* mu2  = (const float*)d_in[8];
    const float* mb1  = (const float*)d_in[9];
    const float* mb2  = (const float*)d_in[10];
    const float* f    = (const float*)d_in[11];
    float* out = (float*)d_out;

    float *gp1, *gp2, *gp3, *gmu1, *gmu2, *gu, *gub;
    cudaGetSymbolAddress((void**)&gp1,  g_p1);
    cudaGetSymbolAddress((void**)&gp2,  g_p2);
    cudaGetSymbolAddress((void**)&gp3,  g_p3);
    cudaGetSymbolAddress((void**)&gmu1, g_mu1);
    cudaGetSymbolAddress((void**)&gmu2, g_mu2);
    cudaGetSymbolAddress((void**)&gu,   g_u);
    cudaGetSymbolAddress((void**)&gub,  g_ub);

    dim3 blk(256);
    dim3 grd((NPIX + 255) / 256);

    // ---- iteration 1: full pipeline (mubar_new & s_new are dead -> never written) ----
    kernA<true><<<grd, blk>>>(ubar, p1, p2, p3, mu1, mu2, s1, s2, mb1, mb2, f,
                              gp1, gp2, gp3, gmu1, gmu2);
    kernB<true><<<grd, blk>>>(u, gp1, gp2, gp3, gu, gub);

    // ---- iteration 2: l2projection & mu are dead code w.r.t. the returned u ----
    kernA<false><<<grd, blk>>>(gub, gp1, gp2, gp3, gmu1, gmu2, s1, s2, mb1, mb2, f,
                               gp1, gp2, gp3, gmu1, gmu2);   // p updated in place (pointwise)
    kernB<false><<<grd, blk>>>(gu, gp1, gp2, gp3, out, gub); // only u is needed
}

// round 4
// speedup vs baseline: 1.5981x; 1.5981x over previous
#include <cuda_runtime.h>
#include <math.h>

#define HH 768
#define WW 768
#define LL 8
#define PP 36
#define NPIX (HH*WW)

#define C_SIGMAP (1.0f / 11.0f)   /* 1/(3+L) */
#define C_LMBDA  0.1f
#define C_NU     0.01f
#define C_TAUU   (1.0f / 6.0f)
#define C_TAUM   (1.0f / 11.0f)   /* 1/(2+PROJ/4) */

// ---- scratch (allocation-free rule: device globals) ----
__device__ float g_p1[NPIX * LL];
__device__ float g_p2[NPIX * LL];
__device__ float g_p3[NPIX * LL];
__device__ float g_ms1[NPIX * LL];   // level-sums of updated mu1 (what iter-2 actually needs)
__device__ float g_ms2[NPIX * LL];
__device__ float g_u [NPIX * LL];
__device__ float g_ub[NPIX * LL];

// K -> (k1,k2) for the upper-triangular combo ordering (k1 outer, k2 inner)
__device__ __host__ constexpr int kk1(int K) {
    int k1 = 0, r = K, c = LL;
    while (r >= c) { r -= c; k1++; c--; }
    return k1;
}
__device__ __host__ constexpr int kk2(int K) {
    int k1 = 0, r = K, c = LL;
    while (r >= c) { r -= c; k1++; c--; }
    return k1 + r;
}

__device__ __forceinline__ void ld8(const float* __restrict__ p, float* v) {
    float4 a = *(const float4*)p;
    float4 b = *(const float4*)(p + 4);
    v[0]=a.x; v[1]=a.y; v[2]=a.z; v[3]=a.w;
    v[4]=b.x; v[5]=b.y; v[6]=b.z; v[7]=b.w;
}
__device__ __forceinline__ void st8(float* __restrict__ p, const float* v) {
    *(float4*)p       = make_float4(v[0], v[1], v[2], v[3]);
    *(float4*)(p + 4) = make_float4(v[4], v[5], v[6], v[7]);
}

// =====================================================================
// Kernel A: parabola projection.
// FULL additionally fuses l2projection + mu-update, emitting the LEVEL
// SUMS of the updated mu (8 floats) instead of the 36-combo mu field.
// =====================================================================
template <bool FULL>
__global__ __launch_bounds__(256)
void kernA(const float* __restrict__ ubar,
           const float* __restrict__ p1i, const float* __restrict__ p2i, const float* __restrict__ p3i,
           const float* __restrict__ mu1i, const float* __restrict__ mu2i,   // FULL: mu fields [PP]; else: level-sums [LL]
           const float* __restrict__ s1i,  const float* __restrict__ s2i,
           const float* __restrict__ mb1i, const float* __restrict__ mb2i,
           const float* __restrict__ f,
           float* __restrict__ p1o, float* __restrict__ p2o, float* __restrict__ p3o,
           float* __restrict__ ms1o, float* __restrict__ ms2o)
{
    int pix = blockIdx.x * blockDim.x + threadIdx.x;
    if (pix >= NPIX) return;
    int w = pix % WW;
    int h = pix / WW;

    // ---- forward differences of ubar (U arrays double as result storage) ----
    float U1[LL], U2[LL], U3[LL];
    {
        float ub[LL];
        ld8(ubar + pix * LL, ub);
        if (h < HH - 1) {
            float nb[LL]; ld8(ubar + (pix + WW) * LL, nb);
            #pragma unroll
            for (int z = 0; z < LL; z++) U1[z] = nb[z] - ub[z];
        } else {
            #pragma unroll
            for (int z = 0; z < LL; z++) U1[z] = 0.0f;
        }
        if (w < WW - 1) {
            float nb[LL]; ld8(ubar + (pix + 1) * LL, nb);
            #pragma unroll
            for (int z = 0; z < LL; z++) U2[z] = nb[z] - ub[z];
        } else {
            #pragma unroll
            for (int z = 0; z < LL; z++) U2[z] = 0.0f;
        }
        #pragma unroll
        for (int z = 0; z < LL; z++) U3[z] = (z < LL - 1) ? (ub[z + 1] - ub[z]) : 0.0f;
    }

    // ---- level sums of mu:  m1s[z] = sum_{K: k1<=z<=k2} mu[K] ----
    float m1s[LL], m2s[LL];
    if (FULL) {
        float d1[LL + 1], d2[LL + 1];
        #pragma unroll
        for (int z = 0; z <= LL; z++) { d1[z] = 0.0f; d2[z] = 0.0f; }
        const float4* m1p = (const float4*)(mu1i + pix * PP);
        const float4* m2p = (const float4*)(mu2i + pix * PP);
        #pragma unroll
        for (int i = 0; i < 9; i++) {
            float4 q1 = m1p[i];
            float4 q2 = m2p[i];
            float v1[4] = {q1.x, q1.y, q1.z, q1.w};
            float v2[4] = {q2.x, q2.y, q2.z, q2.w};
            #pragma unroll
            for (int j = 0; j < 4; j++) {
                const int K = 4 * i + j;
                d1[kk1(K)] += v1[j];  d1[kk2(K) + 1] -= v1[j];
                d2[kk1(K)] += v2[j];  d2[kk2(K) + 1] -= v2[j];
            }
        }
        float a1 = 0.0f, a2 = 0.0f;
        #pragma unroll
        for (int z = 0; z < LL; z++) { a1 += d1[z]; a2 += d2[z]; m1s[z] = a1; m2s[z] = a2; }
    } else {
        ld8(mu1i + pix * LL, m1s);   // precomputed level-sums
        ld8(mu2i + pix * LL, m2s);
    }

    // ---- fold p + sigmap*(diff + musum) into U (frees the p registers) ----
    {
        float pv[LL];
        ld8(p1i + pix * LL, pv);
        #pragma unroll
        for (int z = 0; z < LL; z++) U1[z] = pv[z] + C_SIGMAP * (U1[z] + m1s[z]);
        ld8(p2i + pix * LL, pv);
        #pragma unroll
        for (int z = 0; z < LL; z++) U2[z] = pv[z] + C_SIGMAP * (U2[z] + m2s[z]);
        ld8(p3i + pix * LL, pv);
        #pragma unroll
        for (int z = 0; z < LL; z++) U3[z] = pv[z] + C_SIGMAP * U3[z];
    }

    float fv = __ldg(f + pix);

    // ---- cubic parabola projection, results overwrite U in place ----
    float c1[LL + 1], c2[LL + 1];   // prefix sums of results (used only if FULL)
    c1[0] = 0.0f; c2[0] = 0.0f;
    #pragma unroll
    for (int z = 0; z < LL; z++) {
        float t    = (float)(z + 1) * (1.0f / (float)LL) - fv;
        float quad = C_LMBDA * t * t;
        float n2   = U1[z] * U1[z] + U2[z] * U2[z];
        float B    = 0.25f * n2 - quad;
        if (U3[z] < B) {
            float y   = U3[z] + quad;
            float nrm = sqrtf(n2);
            float a   = 0.5f * nrm;
            float b   = (2.0f / 3.0f) * (1.0f - 0.5f * y);
            float sb  = sqrtf(fmaxf(-b, 0.0f));
            float sb3 = sb * sb * sb;
            float d   = (b < 0.0f) ? (a - sb3) * (a + sb3) : fmaf(b * b, b, a * a);
            float v;
            if (d < 0.0f) {
                // here b<0 strictly, so sb>0
                float ca = fminf(fmaxf(__fdividef(a, sb3), -1.0f), 1.0f);
                v = 2.0f * sb * __cosf(acosf(ca) * (1.0f / 3.0f));
            } else {
                float x  = a + sqrtf(d);               // >= 0
                float c  = (x > 0.0f) ? __powf(x, 1.0f / 3.0f) : 0.0f;
                v = (c == 0.0f) ? 0.0f : (c - __fdividef(b, c));
            }
            float r1, r2;
            if (nrm == 0.0f) { r1 = 0.0f; r2 = 0.0f; }
            else {
                float s = __fdividef(2.0f * v, nrm);
                r1 = s * U1[z]; r2 = s * U2[z];
            }
            U1[z] = r1;
            U2[z] = r2;
            U3[z] = 0.25f * (r1 * r1 + r2 * r2) - quad;
        }
        if (FULL) { c1[z + 1] = c1[z] + U1[z]; c2[z + 1] = c2[z] + U2[z]; }
    }
    st8(p1o + pix * LL, U1);
    st8(p2o + pix * LL, U2);
    st8(p3o + pix * LL, U3);

    // ---- fused l2projection + mu update -> level sums only (iteration 1) ----
    if (FULL) {
        float d1[LL + 1], d2[LL + 1];
        #pragma unroll
        for (int z = 0; z <= LL; z++) { d1[z] = 0.0f; d2[z] = 0.0f; }

        const float4* s1p = (const float4*)(s1i  + pix * PP);
        const float4* s2p = (const float4*)(s2i  + pix * PP);
        const float4* b1p = (const float4*)(mb1i + pix * PP);
        const float4* b2p = (const float4*)(mb2i + pix * PP);

        #pragma unroll
        for (int i = 0; i < 9; i++) {
            float4 qs1 = __ldcs(s1p + i);
            float4 qs2 = __ldcs(s2p + i);
            float4 qb1 = __ldcs(b1p + i);
            float4 qb2 = __ldcs(b2p + i);
            float vs1[4] = {qs1.x, qs1.y, qs1.z, qs1.w};
            float vs2[4] = {qs2.x, qs2.y, qs2.z, qs2.w};
            float vb1[4] = {qb1.x, qb1.y, qb1.z, qb1.w};
            float vb2[4] = {qb2.x, qb2.y, qb2.z, qb2.w};
            #pragma unroll
            for (int j = 0; j < 4; j++) {
                const int K = 4 * i + j;
                // l2projection (SIGMAS = 1)
                float a1 = vs1[j] - vb1[j];
                float a2 = vs2[j] - vb2[j];
                float nr = sqrtf(a1 * a1 + a2 * a2);
                if (nr > C_NU) { float rr = __fdividef(C_NU, nr); a1 *= rr; a2 *= rr; }
                // w = s_proj - t, with t from prefix differences of the new p
                float w1 = a1 - (c1[kk2(K) + 1] - c1[kk1(K)]);
                float w2 = a2 - (c2[kk2(K) + 1] - c2[kk1(K)]);
                d1[kk1(K)] += w1;  d1[kk2(K) + 1] -= w1;
                d2[kk1(K)] += w2;  d2[kk2(K) + 1] -= w2;
            }
        }
        // musum_new[z] = musum_old[z] + tau * prefix(d)[z]
        float a1 = 0.0f, a2 = 0.0f;
        float o1[LL], o2[LL];
        #pragma unroll
        for (int z = 0; z < LL; z++) {
            a1 += d1[z]; a2 += d2[z];
            o1[z] = m1s[z] + C_TAUM * a1;
            o2[z] = m2s[z] + C_TAUM * a2;
        }
        st8(ms1o + pix * LL, o1);
        st8(ms2o + pix * LL, o2);
    }
}

// =====================================================================
// Kernel B: clipping (divergence + clamp + over-relaxation)
// =====================================================================
template <bool WRITE_UBAR>
__global__ __launch_bounds__(256)
void kernB(const float* __restrict__ ui,
           const float* __restrict__ p1, const float* __restrict__ p2, const float* __restrict__ p3,
           float* __restrict__ uo, float* __restrict__ ubo)
{
    int pix = blockIdx.x * blockDim.x + threadIdx.x;
    if (pix >= NPIX) return;
    int w = pix % WW;
    int h = pix / WW;

    float uv[LL];  ld8(ui + pix * LL, uv);
    float p1c[LL]; ld8(p1 + pix * LL, p1c);
    float p2c[LL]; ld8(p2 + pix * LL, p2c);
    float p3c[LL]; ld8(p3 + pix * LL, p3c);

    float p1u[LL], p2l[LL];
    if (h > 0) {
        ld8(p1 + (pix - WW) * LL, p1u);
    } else {
        #pragma unroll
        for (int z = 0; z < LL; z++) p1u[z] = 0.0f;
    }
    if (w > 0) {
        ld8(p2 + (pix - 1) * LL, p2l);
    } else {
        #pragma unroll
        for (int z = 0; z < LL; z++) p2l[z] = 0.0f;
    }

    float ch = (h < HH - 1) ? 1.0f : 0.0f;   // zero last slice along h for p1
    float cw = (w < WW - 1) ? 1.0f : 0.0f;   // zero last slice along w for p2

    float un[LL], ubv[LL];
    #pragma unroll
    for (int z = 0; z < LL; z++) {
        float d1 = ch * p1c[z] - p1u[z];
        float d2 = cw * p2c[z] - p2l[z];
        float d3 = ((z < LL - 1) ? p3c[z] : 0.0f) - ((z > 0) ? p3c[z - 1] : 0.0f);
        float v  = uv[z] + C_TAUU * (d1 + d2 + d3);
        v = fminf(fmaxf(v, 0.0f), 1.0f);
        un[z]  = v;
        ubv[z] = 2.0f * v - uv[z];
    }
    st8(uo + pix * LL, un);
    if (WRITE_UBAR) st8(ubo + pix * LL, ubv);
}

// =====================================================================
extern "C" void kernel_launch(void* const* d_in, const int* in_sizes, int n_in,
                              void* d_out, int out_size)
{
    const float* u    = (const float*)d_in[0];
    const float* ubar = (const float*)d_in[1];
    const float* p1   = (const float*)d_in[2];
    const float* p2   = (const float*)d_in[3];
    const float* p3   = (const float*)d_in[4];
    const float* s1   = (const float*)d_in[5];
    const float* s2   = (const float*)d_in[6];
    const float* mu1  = (const float*)d_in[7];
    const float* mu2  = (const float*)d_in[8];
    const float* mb1  = (const float*)d_in[9];
    const float* mb2  = (const float*)d_in[10];
    const float* f    = (const float*)d_in[11];
    float* out = (float*)d_out;

    float *gp1, *gp2, *gp3, *gms1, *gms2, *gu, *gub;
    cudaGetSymbolAddress((void**)&gp1,  g_p1);
    cudaGetSymbolAddress((void**)&gp2,  g_p2);
    cudaGetSymbolAddress((void**)&gp3,  g_p3);
    cudaGetSymbolAddress((void**)&gms1, g_ms1);
    cudaGetSymbolAddress((void**)&gms2, g_ms2);
    cudaGetSymbolAddress((void**)&gu,   g_u);
    cudaGetSymbolAddress((void**)&gub,  g_ub);

    dim3 blk(256);
    dim3 grd((NPIX + 255) / 256);

    // ---- iteration 1: full pipeline (s_new / mubar_new dead; mu materialized only as level sums) ----
    kernA<true><<<grd, blk>>>(ubar, p1, p2, p3, mu1, mu2, s1, s2, mb1, mb2, f,
                              gp1, gp2, gp3, gms1, gms2);
    kernB<true><<<grd, blk>>>(u, gp1, gp2, gp3, gu, gub);

    // ---- iteration 2: l2projection & mu dead w.r.t. returned u; musum read directly ----
    kernA<false><<<grd, blk>>>(gub, gp1, gp2, gp3, gms1, gms2, s1, s2, mb1, mb2, f,
                               gp1, gp2, gp3, gms1, gms2);   // p updated in place (pointwise)
    kernB<false><<<grd, blk>>>(gu, gp1, gp2, gp3, out, gub); // only u is needed
}